// round 15
// baseline (speedup 1.0000x reference)
#include <cuda_runtime.h>
#include <cuda_fp16.h>
#include <cstdint>

typedef uint32_t u32;

// Problem constants
#define B_    16384
#define S_    200
#define N_    6
#define H_    50
#define T_    5
#define NTOT  205            // 200 encoder + 5 decoder steps
#define THREADS 512          // 16 warps: warp = (mt 0..3 [32 rows], ng 0..3 [16 units])

// A: xh fp16 [128 rows x 64 K], K = 50 h | 6 x | 1 one | 7 zero. Double buffered.
// W: fp16 [2 sets][256 rows x 64 K], row = 4*unit + gate (units 50..63 zero).
#define SM_A0 0
#define SM_A1 16384
#define SM_W  32768           // 2 * 32768 bytes
#define SM_WL 98304           // Wl [6][50] f32 (1200 B)
#define SM_BL 99520           // bl [6] f32
#define SMEM_TOTAL 99648

#define SWZ(o) ((o) ^ (((o) >> 3) & 0x70))

// group barrier: 4 warps (128 threads) sharing rows 32*mt..+31, ids 1..4
#define BARG() asm volatile("bar.sync %0, 128;" :: "r"(mt + 1) : "memory")

__device__ __forceinline__ u32 smem_u32(const void* p) {
    u32 a;
    asm("{ .reg .u64 t; cvta.to.shared.u64 t, %1; cvt.u32.u64 %0, t; }" : "=r"(a) : "l"(p));
    return a;
}
__device__ __forceinline__ float tap(float x) {
    float r; asm("tanh.approx.f32 %0, %1;" : "=f"(r) : "f"(x)); return r;
}
__device__ __forceinline__ float sigm(float x) {   // 0.5*tanh(x/2)+0.5
    return fmaf(tap(0.5f * x), 0.5f, 0.5f);
}

#define LDSM4(r, addr) \
    asm volatile("ldmatrix.sync.aligned.m8n8.x4.shared.b16 {%0,%1,%2,%3}, [%4];" \
        : "=r"((r)[0]), "=r"((r)[1]), "=r"((r)[2]), "=r"((r)[3]) : "r"(addr))

#define MMA16816(d, a, bb0, bb1) \
    asm volatile("mma.sync.aligned.m16n8k16.row.col.f32.f16.f16.f32 " \
        "{%0,%1,%2,%3}, {%4,%5,%6,%7}, {%8,%9}, {%0,%1,%2,%3};" \
        : "+f"((d)[0]), "+f"((d)[1]), "+f"((d)[2]), "+f"((d)[3]) \
        : "r"((a)[0]), "r"((a)[1]), "r"((a)[2]), "r"((a)[3]), "r"(bb0), "r"(bb1))

__global__ void __launch_bounds__(THREADS, 1)
TemPred_kernel(const float* __restrict__ x_seq,
               const float* __restrict__ Wih_e, const float* __restrict__ Whh_e,
               const float* __restrict__ bih_e, const float* __restrict__ bhh_e,
               const float* __restrict__ Wih_d, const float* __restrict__ Whh_d,
               const float* __restrict__ bih_d, const float* __restrict__ bhh_d,
               const float* __restrict__ Wl, const float* __restrict__ bl,
               float* __restrict__ out)
{
    extern __shared__ char smem[];
    const int tid  = threadIdx.x;
    const int wid  = tid >> 5;
    const int lane = tid & 31;
    const int mt   = wid >> 2;        // row group: rows 32*mt .. +31
    const int ng   = wid & 3;         // unit group: units 16*ng .. +15 (8 n8-tiles)
    const int b0   = blockIdx.x * 128;
    const u32 sbase = smem_u32(smem);

    // ---- stage weights fp16 (both sets), row = 4*u + g ----
    for (int idx = tid; idx < 2 * 256 * 64; idx += THREADS) {
        int k    = idx & 63;
        int n    = idx >> 6;          // 0..511
        int set  = n >> 8;
        int rrow = n & 255;
        int u    = rrow >> 2, g = rrow & 3;
        float v = 0.f;
        if (u < H_) {
            int rw = g * H_ + u;
            if (k < H_)      v = (set ? Whh_d : Whh_e)[rw * H_ + k];
            else if (k < 56) v = (set ? Wih_d : Wih_e)[rw * N_ + (k - 50)];
            else if (k == 56) v = set ? (bih_d[rw] + bhh_d[rw]) : (bih_e[rw] + bhh_e[rw]);
        }
        *(__half*)(smem + SM_W + (set << 15) + SWZ((u32)(rrow * 128 + 2 * k))) = __float2half(v);
    }
    for (int i = tid; i < 300; i += THREADS) ((float*)(smem + SM_WL))[i] = Wl[i];
    if (tid < N_) ((float*)(smem + SM_BL))[tid] = bl[tid];
    // zero A0 + A1
    for (int i = tid; i < 8192; i += THREADS) ((u32*)smem)[i] = 0u;
    __syncthreads();

    // per-thread geometry
    const int q     = lane >> 3;
    const u32 rowAo = (u32)((lane & 7) + ((q & 1) << 3));
    const u32 kbA   = (u32)((q >> 1) << 4);
    const int r0    = lane >> 2;
    const int cc    = lane & 3;
    const bool evenc = (cc & 1) == 0;
    const u32 kbB   = (u32)((lane >> 3) << 4);
    const float* Wls = (const float*)(smem + SM_WL);
    const float* bls = (const float*)(smem + SM_BL);

    // x staging duty: warp ng==0 of each group, lanes 0..31 -> row 32*mt+lane
    const bool xduty = (ng == 0);
    const int  xrow  = mt * 32 + lane;
    const int  gl    = tid & 127;

    // bias-one col 56 (both buffers) + x(0) into A0
    if (tid < 128) {
        *(__half*)(smem + SM_A0 + SWZ((u32)(tid * 128 + 112))) = __float2half(1.0f);
        *(__half*)(smem + SM_A1 + SWZ((u32)(tid * 128 + 112))) = __float2half(1.0f);
    }
    if (xduty) {
        const float* xp = x_seq + (size_t)(b0 + xrow) * (S_ * N_);
        *(__half2*)(smem + SM_A0 + SWZ((u32)(xrow * 128 + 100))) = __floats2half2_rn(xp[0], xp[1]);
        *(__half2*)(smem + SM_A0 + SWZ((u32)(xrow * 128 + 104))) = __floats2half2_rn(xp[2], xp[3]);
        *(__half2*)(smem + SM_A0 + SWZ((u32)(xrow * 128 + 108))) = __floats2half2_rn(xp[4], xp[5]);
    }
    __syncthreads();

    // ---- persistent B fragments (weights, encoder set): 8 n8-tiles x 8 regs ----
    u32 bfr[8][8];
    #pragma unroll
    for (int nt = 0; nt < 8; ++nt) {
        const u32 rowB = (u32)(64 * ng + 8 * nt + (lane & 7));
        LDSM4(bfr[nt],     sbase + SM_W + SWZ(rowB * 128 + kbB));
        LDSM4(bfr[nt] + 4, sbase + SM_W + SWZ(rowB * 128 + 64 + kbB));
    }

    float c[16];
    #pragma unroll
    for (int i = 0; i < 16; ++i) c[i] = 0.f;

    int cur = 0;
    for (int t = 0; t < NTOT; ++t) {
        // prefetch next x (encoder only)
        float xv0, xv1, xv2, xv3, xv4, xv5;
        if (xduty && t < S_) {
            int tn = (t + 1 < S_) ? t + 1 : S_ - 1;
            const float* xp = x_seq + (size_t)(b0 + xrow) * (S_ * N_) + tn * N_;
            xv0 = xp[0]; xv1 = xp[1]; xv2 = xp[2]; xv3 = xp[3]; xv4 = xp[4]; xv5 = xp[5];
        }
        // switch persistent weights to decoder set once
        if (t == S_) {
            #pragma unroll
            for (int nt = 0; nt < 8; ++nt) {
                const u32 rowB = (u32)(64 * ng + 8 * nt + (lane & 7));
                LDSM4(bfr[nt],     sbase + SM_W + 32768u + SWZ(rowB * 128 + kbB));
                LDSM4(bfr[nt] + 4, sbase + SM_W + 32768u + SWZ(rowB * 128 + 64 + kbB));
            }
        }

        const u32 abase = sbase + (cur ? SM_A1 : SM_A0);
        char* An = smem + (cur ? SM_A0 : SM_A1);

        #pragma unroll
        for (int mi = 0; mi < 2; ++mi) {
            // A fragments for rows 32*mt + 16*mi .. +15
            u32 a[16];
            const u32 arow = (u32)(32 * mt + 16 * mi) + rowAo;
            #pragma unroll
            for (int kc = 0; kc < 4; ++kc)
                LDSM4(a + 4 * kc, abase + SWZ(arow * 128 + kbA + 32 * kc));

            #pragma unroll
            for (int nt = 0; nt < 8; ++nt) {
                float d[4] = {0.f, 0.f, 0.f, 0.f};
                #pragma unroll
                for (int kc = 0; kc < 4; ++kc)
                    MMA16816(d, a + 4 * kc, bfr[nt][2 * kc], bfr[nt][2 * kc + 1]);

                // one-exchange gate gather: lanes (cc, cc^1) hold complementary
                // gate-pairs of the same unit; swap rows so each lane gets a full cell.
                float x0 = evenc ? d[2] : d[0];
                float x1 = evenc ? d[3] : d[1];
                float y0 = __shfl_xor_sync(0xffffffffu, x0, 1);
                float y1 = __shfl_xor_sync(0xffffffffu, x1, 1);
                float pi = evenc ? d[0] : y0;
                float pf = evenc ? d[1] : y1;
                float pg = evenc ? y0 : d[2];
                float po = evenc ? y1 : d[3];

                float iv = sigm(pi), fv = sigm(pf), gv = tap(pg), ov = sigm(po);
                const int ci = mi * 8 + nt;
                float cn = fmaf(fv, c[ci], iv * gv);
                c[ci] = cn;
                float hv = ov * tap(cn);

                const int ug = 16 * ng + 2 * nt + (cc >> 1);
                if (ug < H_) {
                    const int grow = 32 * mt + 16 * mi + r0 + 8 * (cc & 1);
                    *(__half*)(An + SWZ((u32)(grow * 128 + 2 * ug))) = __float2half(hv);
                }
            }
        }

        if (t < S_) {
            if (xduty) {
                *(__half2*)(An + SWZ((u32)(xrow * 128 + 100))) = __floats2half2_rn(xv0, xv1);
                *(__half2*)(An + SWZ((u32)(xrow * 128 + 104))) = __floats2half2_rn(xv2, xv3);
                *(__half2*)(An + SWZ((u32)(xrow * 128 + 108))) = __floats2half2_rn(xv4, xv5);
            }
        } else {
            // decoder: head reads h from An after group's h stores are visible
            BARG();
            const int dt = t - S_;
            #pragma unroll
            for (int kk = 0; kk < 2; ++kk) {
                const int task = gl + kk * 128;  // 0..255; valid < 192
                if (task < 192) {
                    const int rl  = task & 31;
                    const int m   = task >> 5;
                    const int row = mt * 32 + rl;
                    float s = bls[m];
                    #pragma unroll
                    for (int j = 0; j < 25; ++j) {
                        __half2 hh = *(__half2*)(An + SWZ((u32)(row * 128 + 4 * j)));
                        float2 hf = __half22float2(hh);
                        s = fmaf(Wls[m * H_ + 2 * j],     hf.x, s);
                        s = fmaf(Wls[m * H_ + 2 * j + 1], hf.y, s);
                    }
                    out[(size_t)(b0 + row) * (T_ * N_) + dt * N_ + m] = s;
                    *(__half*)(An + SWZ((u32)(row * 128 + 2 * (50 + m)))) = __float2half(s);
                }
            }
        }

        BARG();                                   // group-local step boundary
        cur ^= 1;
    }
}

extern "C" void kernel_launch(void* const* d_in, const int* in_sizes, int n_in,
                              void* d_out, int out_size)
{
    (void)in_sizes; (void)n_in; (void)out_size;
    const float* x_seq = (const float*)d_in[0];
    const float* Wih_e = (const float*)d_in[1];
    const float* Whh_e = (const float*)d_in[2];
    const float* bih_e = (const float*)d_in[3];
    const float* bhh_e = (const float*)d_in[4];
    const float* Wih_d = (const float*)d_in[5];
    const float* Whh_d = (const float*)d_in[6];
    const float* bih_d = (const float*)d_in[7];
    const float* bhh_d = (const float*)d_in[8];
    const float* Wl    = (const float*)d_in[9];
    const float* bl    = (const float*)d_in[10];
    float* out = (float*)d_out;

    cudaFuncSetAttribute(TemPred_kernel,
                         cudaFuncAttributeMaxDynamicSharedMemorySize, SMEM_TOTAL);
    TemPred_kernel<<<B_ / 128, THREADS, SMEM_TOTAL>>>(
        x_seq, Wih_e, Whh_e, bih_e, bhh_e,
        Wih_d, Whh_d, bih_d, bhh_d, Wl, bl, out);
}

// round 16
// speedup vs baseline: 1.6579x; 1.6579x over previous
#include <cuda_runtime.h>
#include <cuda_fp16.h>
#include <cstdint>

typedef uint32_t u32;

// Problem constants
#define B_    16384
#define S_    200
#define N_    6
#define H_    50
#define T_    5
#define NTOT  205            // 200 encoder + 5 decoder steps
#define THREADS 768          // 24 warps: warp = (mt 0..7 [16 rows], us 0..2 [unit slice])

// A: xh fp16 [128 rows x 64 K], K = 50 h | 6 x | 1 one | 7 zero. Double buffered.
// W: fp16 [2 sets][256 rows x 64 K], row = gate*64 + unit (units 50..63 zero).
#define SM_A0 0
#define SM_A1 16384
#define SM_W  32768           // 2 * 32768 bytes
#define SM_WL 98304           // Wl [6][50] f32 (1200 B)
#define SM_BL 99520           // bl [6] f32
#define SMEM_TOTAL 99648

#define SWZ(o) ((o) ^ (((o) >> 3) & 0x70))

// trio barrier: 3 warps (96 threads) sharing rows 16*mt..+15, ids 1..8
#define BARP() asm volatile("bar.sync %0, 96;" :: "r"(mt + 1) : "memory")

__device__ __forceinline__ u32 smem_u32(const void* p) {
    u32 a;
    asm("{ .reg .u64 t; cvta.to.shared.u64 t, %1; cvt.u32.u64 %0, t; }" : "=r"(a) : "l"(p));
    return a;
}
__device__ __forceinline__ float tap(float x) {
    float r; asm("tanh.approx.f32 %0, %1;" : "=f"(r) : "f"(x)); return r;
}
__device__ __forceinline__ float sigm(float x) {   // 0.5*tanh(x/2)+0.5
    return fmaf(tap(0.5f * x), 0.5f, 0.5f);
}

#define LDSM4(r, addr) \
    asm volatile("ldmatrix.sync.aligned.m8n8.x4.shared.b16 {%0,%1,%2,%3}, [%4];" \
        : "=r"((r)[0]), "=r"((r)[1]), "=r"((r)[2]), "=r"((r)[3]) : "r"(addr))

#define MMA16816(d, a, bb0, bb1) \
    asm volatile("mma.sync.aligned.m16n8k16.row.col.f32.f16.f16.f32 " \
        "{%0,%1,%2,%3}, {%4,%5,%6,%7}, {%8,%9}, {%0,%1,%2,%3};" \
        : "+f"((d)[0]), "+f"((d)[1]), "+f"((d)[2]), "+f"((d)[3]) \
        : "r"((a)[0]), "r"((a)[1]), "r"((a)[2]), "r"((a)[3]), "r"(bb0), "r"(bb1))

__global__ void __launch_bounds__(THREADS, 1)
TemPred_kernel(const float* __restrict__ x_seq,
               const float* __restrict__ Wih_e, const float* __restrict__ Whh_e,
               const float* __restrict__ bih_e, const float* __restrict__ bhh_e,
               const float* __restrict__ Wih_d, const float* __restrict__ Whh_d,
               const float* __restrict__ bih_d, const float* __restrict__ bhh_d,
               const float* __restrict__ Wl, const float* __restrict__ bl,
               float* __restrict__ out)
{
    extern __shared__ char smem[];
    const int tid  = threadIdx.x;
    const int wid  = tid >> 5;
    const int lane = tid & 31;
    const int mt   = wid / 3;         // m-tile: rows 16*mt .. +15 (trio id, 0..7)
    const int us   = wid % 3;         // unit slice: 0:{0,8} 1:{16,24} 2:{32,40,48}
    const int b0   = blockIdx.x * 128;
    const u32 sbase = smem_u32(smem);

    // ---- stage weights fp16 (both sets) ----
    for (int idx = tid; idx < 2 * 256 * 64; idx += THREADS) {
        int k    = idx & 63;
        int n    = idx >> 6;          // 0..511
        int set  = n >> 8;
        int rrow = n & 255;
        int g    = rrow >> 6, u = rrow & 63;
        float v = 0.f;
        if (u < H_) {
            int rw = g * H_ + u;
            if (k < H_)      v = (set ? Whh_d : Whh_e)[rw * H_ + k];
            else if (k < 56) v = (set ? Wih_d : Wih_e)[rw * N_ + (k - 50)];
            else if (k == 56) v = set ? (bih_d[rw] + bhh_d[rw]) : (bih_e[rw] + bhh_e[rw]);
        }
        *(__half*)(smem + SM_W + (set << 15) + SWZ((u32)(rrow * 128 + 2 * k))) = __float2half(v);
    }
    for (int i = tid; i < 300; i += THREADS) ((float*)(smem + SM_WL))[i] = Wl[i];
    if (tid < N_) ((float*)(smem + SM_BL))[tid] = bl[tid];
    // zero A0 + A1
    for (int i = tid; i < 8192; i += THREADS) ((u32*)smem)[i] = 0u;
    __syncthreads();

    // per-thread geometry
    const int q     = lane >> 3;
    const u32 rowA  = (u32)(mt * 16 + (lane & 7) + ((q & 1) << 3));
    const u32 kbA   = (u32)((q >> 1) << 4);
    const int csel  = lane & 3;                 // column pair selector
    const int r0    = mt * 16 + (lane >> 2);    // first D row
    const int ubase = us * 16;                  // 0,16,32
    const int noct  = (us == 2) ? 3 : 2;
    const float* Wls = (const float*)(smem + SM_WL);
    const float* bls = (const float*)(smem + SM_BL);

    // x staging duty: trio-local — us==0, lane<16 handles row 16*mt+lane
    const bool xduty = (us == 0) && (lane < 16);
    const int  xrow  = mt * 16 + lane;

    // bias-one col 56 (both buffers) + x(0) into A0
    if (tid < 128) {
        *(__half*)(smem + SM_A0 + SWZ((u32)(tid * 128 + 112))) = __float2half(1.0f);
        *(__half*)(smem + SM_A1 + SWZ((u32)(tid * 128 + 112))) = __float2half(1.0f);
    }
    if (xduty) {
        const float* xp = x_seq + (size_t)(b0 + xrow) * (S_ * N_);
        *(__half2*)(smem + SM_A0 + SWZ((u32)(xrow * 128 + 100))) = __floats2half2_rn(xp[0], xp[1]);
        *(__half2*)(smem + SM_A0 + SWZ((u32)(xrow * 128 + 104))) = __floats2half2_rn(xp[2], xp[3]);
        *(__half2*)(smem + SM_A0 + SWZ((u32)(xrow * 128 + 108))) = __floats2half2_rn(xp[4], xp[5]);
    }
    __syncthreads();

    float c[12];
    #pragma unroll
    for (int i = 0; i < 12; ++i) c[i] = 0.f;

    int cur = 0;
    for (int t = 0; t < NTOT; ++t) {
        // prefetch next x (encoder only)
        float xv0, xv1, xv2, xv3, xv4, xv5;
        if (xduty && t < S_) {
            int tn = (t + 1 < S_) ? t + 1 : S_ - 1;
            const float* xp = x_seq + (size_t)(b0 + xrow) * (S_ * N_) + tn * N_;
            xv0 = xp[0]; xv1 = xp[1]; xv2 = xp[2]; xv3 = xp[3]; xv4 = xp[4]; xv5 = xp[5];
        }

        const u32 abase = sbase + (cur ? SM_A1 : SM_A0);
        char* An = smem + (cur ? SM_A0 : SM_A1);
        const u32 wbase = sbase + SM_W + ((t >= S_) ? 32768u : 0u);

        // A fragments: 4 k-chunks of 16
        u32 a[16];
        #pragma unroll
        for (int kc = 0; kc < 4; ++kc)
            LDSM4(a + 4 * kc, abase + SWZ(rowA * 128 + kbA + 32 * kc));

        #pragma unroll
        for (int oct = 0; oct < 3; ++oct) {
            if (oct >= noct) break;
            const int u0 = ubase + oct * 8;
            const int uA = u0 + 2 * csel;
            const u32 kbB = (u32)((lane >> 3) << 4);

            float iv[4], pc[4];   // carried from gate-pair 0 to 1

            // ---- gate pair 0: i (g=0), f (g=1) ----
            {
                u32 b0r[8], b1r[8];
                const u32 ri = (u32)(0 * 64 + u0 + (lane & 7));
                const u32 rf = (u32)(1 * 64 + u0 + (lane & 7));
                LDSM4(b0r,     wbase + SWZ(ri * 128 + kbB));
                LDSM4(b0r + 4, wbase + SWZ(ri * 128 + 64 + kbB));
                LDSM4(b1r,     wbase + SWZ(rf * 128 + kbB));
                LDSM4(b1r + 4, wbase + SWZ(rf * 128 + 64 + kbB));
                float d0[4] = {0.f, 0.f, 0.f, 0.f};
                float d1[4] = {0.f, 0.f, 0.f, 0.f};
                #pragma unroll
                for (int kc = 0; kc < 4; ++kc) {
                    MMA16816(d0, a + 4 * kc, b0r[2 * kc], b0r[2 * kc + 1]);
                    MMA16816(d1, a + 4 * kc, b1r[2 * kc], b1r[2 * kc + 1]);
                }
                #pragma unroll
                for (int e = 0; e < 4; ++e) {
                    iv[e] = sigm(d0[e]);
                    pc[e] = sigm(d1[e]) * c[oct * 4 + e];
                }
            }

            // ---- gate pair 1: g (g=2), o (g=3) ----
            {
                u32 b0r[8], b1r[8];
                const u32 rg = (u32)(2 * 64 + u0 + (lane & 7));
                const u32 ro = (u32)(3 * 64 + u0 + (lane & 7));
                LDSM4(b0r,     wbase + SWZ(rg * 128 + kbB));
                LDSM4(b0r + 4, wbase + SWZ(rg * 128 + 64 + kbB));
                LDSM4(b1r,     wbase + SWZ(ro * 128 + kbB));
                LDSM4(b1r + 4, wbase + SWZ(ro * 128 + 64 + kbB));
                float d0[4] = {0.f, 0.f, 0.f, 0.f};
                float d1[4] = {0.f, 0.f, 0.f, 0.f};
                #pragma unroll
                for (int kc = 0; kc < 4; ++kc) {
                    MMA16816(d0, a + 4 * kc, b0r[2 * kc], b0r[2 * kc + 1]);
                    MMA16816(d1, a + 4 * kc, b1r[2 * kc], b1r[2 * kc + 1]);
                }
                float h[4];
                #pragma unroll
                for (int e = 0; e < 4; ++e) {
                    float cn = fmaf(iv[e], tap(d0[e]), pc[e]);
                    c[oct * 4 + e] = cn;
                    h[e] = sigm(d1[e]) * tap(cn);
                }
                if (uA < H_) {                   // pair (uA, uA+1) valid (50 is even)
                    *(__half2*)(An + SWZ((u32)(r0 * 128 + 2 * uA)))       = __floats2half2_rn(h[0], h[1]);
                    *(__half2*)(An + SWZ((u32)((r0 + 8) * 128 + 2 * uA))) = __floats2half2_rn(h[2], h[3]);
                }
            }
        }

        if (t < S_) {
            if (xduty) {
                *(__half2*)(An + SWZ((u32)(xrow * 128 + 100))) = __floats2half2_rn(xv0, xv1);
                *(__half2*)(An + SWZ((u32)(xrow * 128 + 104))) = __floats2half2_rn(xv2, xv3);
                *(__half2*)(An + SWZ((u32)(xrow * 128 + 108))) = __floats2half2_rn(xv4, xv5);
            }
        } else {
            // decoder: head reads h from An after trio's h stores are visible
            BARP();
            const int dt = t - S_;
            const int pt = us * 32 + lane;       // 0..95 within trio: exactly 96 tasks
            {
                const int rloc = pt & 15;
                const int m    = pt >> 4;        // 0..5
                const int row  = mt * 16 + rloc;
                float s = bls[m];
                #pragma unroll
                for (int j = 0; j < 25; ++j) {
                    __half2 hh = *(__half2*)(An + SWZ((u32)(row * 128 + 4 * j)));
                    float2 hf = __half22float2(hh);
                    s = fmaf(Wls[m * H_ + 2 * j],     hf.x, s);
                    s = fmaf(Wls[m * H_ + 2 * j + 1], hf.y, s);
                }
                out[(size_t)(b0 + row) * (T_ * N_) + dt * N_ + m] = s;
                *(__half*)(An + SWZ((u32)(row * 128 + 2 * (50 + m)))) = __float2half(s);
            }
        }

        BARP();                                   // trio-local step boundary
        cur ^= 1;
    }
}

extern "C" void kernel_launch(void* const* d_in, const int* in_sizes, int n_in,
                              void* d_out, int out_size)
{
    (void)in_sizes; (void)n_in; (void)out_size;
    const float* x_seq = (const float*)d_in[0];
    const float* Wih_e = (const float*)d_in[1];
    const float* Whh_e = (const float*)d_in[2];
    const float* bih_e = (const float*)d_in[3];
    const float* bhh_e = (const float*)d_in[4];
    const float* Wih_d = (const float*)d_in[5];
    const float* Whh_d = (const float*)d_in[6];
    const float* bih_d = (const float*)d_in[7];
    const float* bhh_d = (const float*)d_in[8];
    const float* Wl    = (const float*)d_in[9];
    const float* bl    = (const float*)d_in[10];
    float* out = (float*)d_out;

    cudaFuncSetAttribute(TemPred_kernel,
                         cudaFuncAttributeMaxDynamicSharedMemorySize, SMEM_TOTAL);
    TemPred_kernel<<<B_ / 128, THREADS, SMEM_TOTAL>>>(
        x_seq, Wih_e, Whh_e, bih_e, bhh_e,
        Wih_d, Whh_d, bih_d, bhh_d, Wl, bl, out);
}